// round 4
// baseline (speedup 1.0000x reference)
#include <cuda_runtime.h>

// Problem constants
#define MM 512
#define NN 768
#define TILE 32
#define KC 128
#define KS (NN / KC)                 // 6 k-chunks
#define NT (MM / TILE)               // 16 tile rows
#define NTILES (NT * (NT + 1) / 2)   // 136 upper-tri tiles (incl diagonal)

// Scratch: partial sum-of-squares matrix S[i][j]
__device__ float g_S[MM * MM];

// GT may arrive as int32 or int64 depending on JAX x64 config.
// For int64 little-endian values < 2^31, the int32 view has 0 in odd slots.
// arange GT has GT[1]==1 when int32 => detect via GT32[1]==0.
__device__ __forceinline__ int gather_idx(const int* __restrict__ GT32, int r, int is64) {
    if (is64) return (int)(((const long long*)GT32)[r]);
    return GT32[r];
}

// ---------------------------------------------------------------------------
// Zero S and the output scalar
// ---------------------------------------------------------------------------
__global__ void __launch_bounds__(256) zero_kernel(float* __restrict__ out) {
    int idx = blockIdx.x * blockDim.x + threadIdx.x;   // 65536 threads, one float4 each
    float4 z = make_float4(0.f, 0.f, 0.f, 0.f);
    ((float4*)g_S)[idx] = z;
    if (idx == 0) *out = 0.f;
}

// ---------------------------------------------------------------------------
// Phase 1: accumulate S[i][j] += sum_k relu(r_i[k]-r_j[k])^2 over one k-chunk
// grid = (NTILES, KS), block = 64 threads, 4x4 register micro-tile
// ---------------------------------------------------------------------------
__global__ void __launch_bounds__(64) phase1_kernel(const float* __restrict__ repr,
                                                    const int* __restrict__ GT32) {
    // Decode upper-triangular tile index -> (bi, bj), bi <= bj
    int t = blockIdx.x;
    int bi = 0, rem = t;
    #pragma unroll
    for (int r = 0; r < NT; ++r) {
        int cnt = NT - r;
        if (rem < cnt) { bi = r; break; }
        rem -= cnt;
    }
    int bj = bi + rem;
    int k0 = blockIdx.y * KC;

    __shared__ float sA[TILE][KC + 4];   // stride 132 floats (16B multiple, de-conflicts)
    __shared__ float sB[TILE][KC + 4];

    const int tid = threadIdx.x;
    const int is64 = (GT32[1] == 0);

    // Cooperative tile load: 32 rows x 128 floats per tile, float4-coalesced
    for (int e = tid; e < TILE * (KC / 4); e += 64) {
        int r = e >> 5;          // row within tile (KC/4 == 32 float4 per row)
        int c = e & 31;          // float4 column
        int gi = gather_idx(GT32, bi * TILE + r, is64);
        float4 va = *(const float4*)(repr + (size_t)gi * NN + k0 + c * 4);
        *(float4*)&sA[r][c * 4] = va;
        int gj = gather_idx(GT32, bj * TILE + r, is64);
        float4 vb = *(const float4*)(repr + (size_t)gj * NN + k0 + c * 4);
        *(float4*)&sB[r][c * 4] = vb;
    }
    __syncthreads();

    const int ti = tid >> 3;   // 0..7 -> rows 4*ti..4*ti+3
    const int tj = tid & 7;    // 0..7 -> cols 4*tj..4*tj+3

    float acc[4][4];
    #pragma unroll
    for (int i = 0; i < 4; ++i)
        #pragma unroll
        for (int j = 0; j < 4; ++j) acc[i][j] = 0.f;

    #pragma unroll 4
    for (int kk = 0; kk < KC; kk += 4) {
        float4 a[4], b[4];
        #pragma unroll
        for (int i = 0; i < 4; ++i) a[i] = *(const float4*)&sA[4 * ti + i][kk];
        #pragma unroll
        for (int j = 0; j < 4; ++j) b[j] = *(const float4*)&sB[4 * tj + j][kk];

        #pragma unroll
        for (int i = 0; i < 4; ++i) {
            #pragma unroll
            for (int j = 0; j < 4; ++j) {
                float d0 = a[i].x - b[j].x;
                float d1 = a[i].y - b[j].y;
                float d2 = a[i].z - b[j].z;
                float d3 = a[i].w - b[j].w;
                d0 = fmaxf(d0, 0.f);
                d1 = fmaxf(d1, 0.f);
                d2 = fmaxf(d2, 0.f);
                d3 = fmaxf(d3, 0.f);
                acc[i][j] = fmaf(d0, d0, acc[i][j]);
                acc[i][j] = fmaf(d1, d1, acc[i][j]);
                acc[i][j] = fmaf(d2, d2, acc[i][j]);
                acc[i][j] = fmaf(d3, d3, acc[i][j]);
            }
        }
    }

    // Accumulate partials into S (k-chunks collide -> atomics; low contention)
    #pragma unroll
    for (int i = 0; i < 4; ++i) {
        int gi = bi * TILE + 4 * ti + i;
        #pragma unroll
        for (int j = 0; j < 4; ++j) {
            int gj = bj * TILE + 4 * tj + j;
            atomicAdd(&g_S[gi * MM + gj], acc[i][j]);
        }
    }
}

// ---------------------------------------------------------------------------
// Phase 2: out = sum_{i<j} sqrt(S[i][j])
// ---------------------------------------------------------------------------
__global__ void __launch_bounds__(256) phase2_kernel(float* __restrict__ out) {
    __shared__ float red[256];
    float local = 0.f;
    for (int idx = blockIdx.x * blockDim.x + threadIdx.x; idx < MM * MM;
         idx += gridDim.x * blockDim.x) {
        int i = idx >> 9;       // / 512
        int j = idx & (MM - 1); // % 512
        if (i < j) local += sqrtf(g_S[idx]);
    }
    red[threadIdx.x] = local;
    __syncthreads();
    #pragma unroll
    for (int s = 128; s > 0; s >>= 1) {
        if (threadIdx.x < s) red[threadIdx.x] += red[threadIdx.x + s];
        __syncthreads();
    }
    if (threadIdx.x == 0) atomicAdd(out, red[0]);
}

// ---------------------------------------------------------------------------
extern "C" void kernel_launch(void* const* d_in, const int* in_sizes, int n_in,
                              void* d_out, int out_size) {
    const float* repr = (const float*)d_in[0];
    const int* GT32 = (const int*)d_in[1];
    float* out = (float*)d_out;

    // 1) zero S and output (65536 threads x float4 = 1 MB)
    zero_kernel<<<256, 256>>>(out);

    // 2) pairwise relu-diff sum-of-squares, k-split
    dim3 grid1(NTILES, KS);
    phase1_kernel<<<grid1, 64>>>(repr, GT32);

    // 3) masked sqrt + reduce
    phase2_kernel<<<256, 256>>>(out);
}

// round 8
// speedup vs baseline: 1.8889x; 1.8889x over previous
#include <cuda_runtime.h>

// Problem constants
#define MM 512
#define NN 768
#define TILE 32
#define KC 128
#define KS (NN / KC)                 // 6 k-chunks
#define NT (MM / TILE)               // 16 tile rows
#define NTILES (NT * (NT + 1) / 2)   // 136 upper-tri tiles (incl diagonal)

// Scratch: partial sum-of-squares matrix S[i][j].
// Zero at module load; phase2 re-zeroes after reading -> clean for every replay.
__device__ float g_S[MM * MM];

// GT may arrive as int32 or int64. For little-endian int64 arange, GT32[1]==0.
__device__ __forceinline__ int gather_idx(const int* __restrict__ GT32, int r, int is64) {
    if (is64) return (int)(((const long long*)GT32)[r]);
    return GT32[r];
}

// ---- packed f32x2 helpers (FADD2 / FFMA2 on sm_103a) ----------------------
__device__ __forceinline__ unsigned long long f2_add(unsigned long long a,
                                                     unsigned long long b) {
    unsigned long long r;
    asm("add.rn.f32x2 %0, %1, %2;" : "=l"(r) : "l"(a), "l"(b));
    return r;
}
__device__ __forceinline__ unsigned long long f2_relu(unsigned long long e) {
    union { unsigned long long u; float2 f; } t;
    t.u = e;
    t.f.x = fmaxf(t.f.x, 0.f);   // FMNMX on the pair halves (no MOVs: same regs)
    t.f.y = fmaxf(t.f.y, 0.f);
    return t.u;
}
__device__ __forceinline__ void f2_fma_acc(unsigned long long& acc,
                                           unsigned long long g) {
    asm("fma.rn.f32x2 %0, %1, %2, %0;" : "+l"(acc) : "l"(g), "l"(g));
}

// ---------------------------------------------------------------------------
// Phase 1: S[i][j] += sum_k relu(r_i[k]-r_j[k])^2 over one 128-wide k-chunk.
// grid = (136 upper-tri tiles, 6 k-chunks), 64 threads, 4x4 register micro-tile.
// Smem: row-major tiles with XOR chunk swizzle (conflict-free LDS.128 for both
// the j-spread B loads and the i-spread A loads). B is stored NEGATED so the
// packed diff is a single add.rn.f32x2.
// ---------------------------------------------------------------------------
__global__ void __launch_bounds__(64) phase1_kernel(const float* __restrict__ repr,
                                                    const int* __restrict__ GT32,
                                                    float* __restrict__ out) {
    // upper-triangular tile decode
    int t = blockIdx.x;
    int bi = 0, rem = t;
    #pragma unroll
    for (int r = 0; r < NT; ++r) {
        int cnt = NT - r;
        if (rem < cnt) { bi = r; break; }
        rem -= cnt;
    }
    int bj = bi + rem;
    int k0 = blockIdx.y * KC;

    // reset the output accumulator for this replay (finishes before phase2 launches)
    if (blockIdx.x == 0 && blockIdx.y == 0 && threadIdx.x == 0) *out = 0.f;

    __shared__ float sA[TILE * KC];   // 16 KB, swizzled row-major
    __shared__ float sB[TILE * KC];   // 16 KB, swizzled row-major, negated

    const int tid = threadIdx.x;
    const int is64 = (GT32[1] == 0);

    // Cooperative fill: 32 rows x 32 float4-chunks per tile.
    // phys_chunk = chunk ^ ((row>>2)&7)
    for (int e = tid; e < TILE * (KC / 4); e += 64) {
        int r = e >> 5;           // row 0..31
        int c = e & 31;           // logical chunk 0..31
        int dst = r * KC + ((c ^ ((r >> 2) & 7)) << 2);
        int gi = gather_idx(GT32, bi * TILE + r, is64);
        float4 va = *(const float4*)(repr + (size_t)gi * NN + k0 + c * 4);
        *(float4*)&sA[dst] = va;
        int gj = gather_idx(GT32, bj * TILE + r, is64);
        float4 vb = *(const float4*)(repr + (size_t)gj * NN + k0 + c * 4);
        vb.x = -vb.x; vb.y = -vb.y; vb.z = -vb.z; vb.w = -vb.w;
        *(float4*)&sB[dst] = vb;
    }
    __syncthreads();

    const int ti = tid >> 3;   // 0..7 -> rows 4*ti..4*ti+3
    const int tj = tid & 7;    // 0..7 -> cols 4*tj..4*tj+3

    union F4 { float4 v; unsigned long long p[2]; };

    unsigned long long acc[4][4];
    #pragma unroll
    for (int i = 0; i < 4; ++i)
        #pragma unroll
        for (int j = 0; j < 4; ++j) acc[i][j] = 0ull;   // packed (0,0)

    #pragma unroll 2
    for (int kc = 0; kc < KC / 4; ++kc) {
        F4 a[4], b[4];
        int ca = (kc ^ ti) << 2;   // swizzled chunk for A rows (ti const/thread)
        int cb = (kc ^ tj) << 2;   // swizzled chunk for B rows
        #pragma unroll
        for (int i = 0; i < 4; ++i) a[i].v = *(const float4*)&sA[(4 * ti + i) * KC + ca];
        #pragma unroll
        for (int j = 0; j < 4; ++j) b[j].v = *(const float4*)&sB[(4 * tj + j) * KC + cb];

        #pragma unroll
        for (int i = 0; i < 4; ++i) {
            #pragma unroll
            for (int j = 0; j < 4; ++j) {
                // d = a - b (b pre-negated): packed over k-pairs
                unsigned long long e0 = f2_add(a[i].p[0], b[j].p[0]);
                f2_fma_acc(acc[i][j], f2_relu(e0));
                unsigned long long e1 = f2_add(a[i].p[1], b[j].p[1]);
                f2_fma_acc(acc[i][j], f2_relu(e1));
            }
        }
    }

    // epilogue: fold packed halves, one atomic per (i,j)
    #pragma unroll
    for (int i = 0; i < 4; ++i) {
        int gi = bi * TILE + 4 * ti + i;
        #pragma unroll
        for (int j = 0; j < 4; ++j) {
            int gj = bj * TILE + 4 * tj + j;
            union { unsigned long long u; float2 f; } s;
            s.u = acc[i][j];
            atomicAdd(&g_S[gi * MM + gj], s.f.x + s.f.y);
        }
    }
}

// ---------------------------------------------------------------------------
// Phase 2: out = sum_{i<j} sqrt(S[i][j]); also re-zeroes g_S for next replay.
// 256 blocks x 256 threads: exactly one float4 of S per thread.
// ---------------------------------------------------------------------------
__global__ void __launch_bounds__(256) phase2_kernel(float* __restrict__ out) {
    int idx4 = blockIdx.x * 256 + threadIdx.x;      // 0..65535
    float4* S4 = (float4*)g_S;
    float4 v = S4[idx4];
    S4[idx4] = make_float4(0.f, 0.f, 0.f, 0.f);     // self-clean

    int i = idx4 >> 7;            // row (512 floats = 128 float4)
    int j0 = (idx4 & 127) << 2;   // first column of this float4

    float local = 0.f;
    if (j0 + 0 > i) local += sqrtf(v.x);
    if (j0 + 1 > i) local += sqrtf(v.y);
    if (j0 + 2 > i) local += sqrtf(v.z);
    if (j0 + 3 > i) local += sqrtf(v.w);

    // warp reduce
    #pragma unroll
    for (int s = 16; s > 0; s >>= 1)
        local += __shfl_xor_sync(0xffffffffu, local, s);

    __shared__ float red[8];
    if ((threadIdx.x & 31) == 0) red[threadIdx.x >> 5] = local;
    __syncthreads();
    if (threadIdx.x < 8) {
        float w = red[threadIdx.x];
        #pragma unroll
        for (int s = 4; s > 0; s >>= 1)
            w += __shfl_xor_sync(0xffu, w, s);
        if (threadIdx.x == 0) atomicAdd(out, w);
    }
}

// ---------------------------------------------------------------------------
extern "C" void kernel_launch(void* const* d_in, const int* in_sizes, int n_in,
                              void* d_out, int out_size) {
    const float* repr = (const float*)d_in[0];
    const int* GT32 = (const int*)d_in[1];
    float* out = (float*)d_out;

    dim3 grid1(NTILES, KS);
    phase1_kernel<<<grid1, 64>>>(repr, GT32, out);
    phase2_kernel<<<256, 256>>>(out);
}